// round 10
// baseline (speedup 1.0000x reference)
#include <cuda_runtime.h>

#define TE 8
#define NODES_MAX 50000

typedef unsigned long long ull;

__device__ float g_agg_s[(size_t)NODES_MAX * 64];
__device__ float g_agg_v[(size_t)NODES_MAX * 192];

__device__ __forceinline__ ull ffma2(ull a, ull b, ull c) {
  ull d;
  asm("fma.rn.f32x2 %0, %1, %2, %3;" : "=l"(d) : "l"(a), "l"(b), "l"(c));
  return d;
}
__device__ __forceinline__ ull pack2(float x) {
  ull d;
  asm("mov.b64 %0, {%1, %1};" : "=l"(d) : "f"(x));
  return d;
}
__device__ __forceinline__ void upk8(const ull* a, float* f) {
#pragma unroll
  for (int j = 0; j < 4; j++) {
    f[2 * j]     = __int_as_float((int)(unsigned)(a[j] & 0xffffffffull));
    f[2 * j + 1] = __int_as_float((int)(unsigned)(a[j] >> 32));
  }
}
__device__ __forceinline__ float sigm(float x) { return 1.0f / (1.0f + __expf(-x)); }
__device__ __forceinline__ float4 ldg4(const float* base, int o4) {
  return __ldg(reinterpret_cast<const float4*>(base) + o4);
}

#define RSQRT3 0.5773502692f
#define INV1   0.0622573010f   // 1/sqrt(258)
#define INV2   0.0883883476f   // 1/sqrt(128)
#define INV0   0.0625f         // 1/sqrt(256)
#define INVU   0.0883883476f   // 1/sqrt(128)

// one smem row (8 edges, broadcast) feeds FOUR output columns; acc = ull[16]
__device__ __forceinline__ void accRow4(const float* __restrict__ r, float4 w,
                                        ull* a) {
  ulonglong2 r0 = *reinterpret_cast<const ulonglong2*>(r);
  ulonglong2 r1 = *reinterpret_cast<const ulonglong2*>(r + 4);
  ull w0 = pack2(w.x), w1 = pack2(w.y), w2 = pack2(w.z), w3 = pack2(w.w);
  a[0]  = ffma2(r0.x, w0, a[0]);  a[1]  = ffma2(r0.y, w0, a[1]);
  a[2]  = ffma2(r1.x, w0, a[2]);  a[3]  = ffma2(r1.y, w0, a[3]);
  a[4]  = ffma2(r0.x, w1, a[4]);  a[5]  = ffma2(r0.y, w1, a[5]);
  a[6]  = ffma2(r1.x, w1, a[6]);  a[7]  = ffma2(r1.y, w1, a[7]);
  a[8]  = ffma2(r0.x, w2, a[8]);  a[9]  = ffma2(r0.y, w2, a[9]);
  a[10] = ffma2(r1.x, w2, a[10]); a[11] = ffma2(r1.y, w2, a[11]);
  a[12] = ffma2(r0.x, w3, a[12]); a[13] = ffma2(r0.y, w3, a[13]);
  a[14] = ffma2(r1.x, w3, a[14]); a[15] = ffma2(r1.y, w3, a[15]);
}

// R=4 GEMM, runtime row-stride rs (uniform code across mixed-role warps).
template <int K, int LDW>
__device__ __forceinline__ void gemmR4(const float* __restrict__ W, int o4,
                                       const float* __restrict__ row, int rs,
                                       ull* a) {
#pragma unroll 1
  for (int k0 = 0; k0 < K; k0 += 4) {
    float4 w[4];
#pragma unroll
    for (int j = 0; j < 4; j++)
      w[j] = __ldg(reinterpret_cast<const float4*>(W + (size_t)(k0 + j) * LDW) + o4);
#pragma unroll
    for (int j = 0; j < 4; j++)
      accRow4(row + (size_t)(k0 + j) * rs, w[j], a);
  }
}

// ---------------------------------------------------------------------------
// Edge kernel: 8 edges/CTA, 128 threads, R=4, fused scalar+vector phases.
// warp0=SS, warp1=VS, warp2=q0|q1, warp3=q2|p (branchless half-warp roles).
// ---------------------------------------------------------------------------
__global__ void __launch_bounds__(128, 5) edge_kernel(
    const float* __restrict__ node_s, const float* __restrict__ node_v,
    const float* __restrict__ eas, const float* __restrict__ eav,
    const float* __restrict__ add_feat,
    const float* __restrict__ Wss1, const float* __restrict__ Wvs1,
    const float* __restrict__ Wsv1, const float* __restrict__ Wvv1,
    const float* __restrict__ b1,
    const float* __restrict__ Wss2, const float* __restrict__ Wvs2,
    const float* __restrict__ Wsv2, const float* __restrict__ Wvv2,
    const float* __restrict__ b2,
    const int* __restrict__ senders, const int* __restrict__ receivers,
    int E)
{
  __shared__ __align__(16) float xs_rT[130][TE];
  __shared__ __align__(16) float d1T[128][TE];      // d1; m2 exchange
  __shared__ __align__(16) float xvT[128][3][TE];
  __shared__ __align__(16) float ms_rT[64][TE];
  __shared__ __align__(16) float gT[64][TE];
  __shared__ __align__(16) float d2T[64][TE];
  __shared__ __align__(16) float mvT[64][3][TE];    // mv; m1 exchange
  __shared__ __align__(16) float pT[64][TE];
  __shared__ float asx[TE];
  __shared__ float avx[3][TE];
  __shared__ int sndx[TE], rcvx[TE];

  const int tid = threadIdx.x;
  const int wid = tid >> 5, lane = tid & 31;
  const int half = lane >> 4;      // role within mixed warps
  const int o4v = lane & 15;       // vector output group (x4)
  const int e0 = blockIdx.x * TE;

  if (tid < TE) {
    int ge = e0 + tid;
    bool val = ge < E;
    sndx[tid] = val ? senders[ge] : 0;
    rcvx[tid] = val ? receivers[ge] : -1;
    asx[tid]  = val ? eas[ge] : 0.f;
#pragma unroll
    for (int i = 0; i < 3; i++) avx[i][tid] = val ? eav[ge * 3 + i] : 0.f;
  }
  __syncthreads();

  for (int idx = tid; idx < TE * 130; idx += 128) {
    int e = idx / 130, s = idx - e * 130;
    int r = rcvx[e] < 0 ? 0 : rcvx[e];
    float v;
    if (s < 64)       v = __ldg(node_s + (size_t)sndx[e] * 64 + s);
    else if (s < 128) v = __ldg(node_s + (size_t)r * 64 + (s - 64));
    else {
      int ge = e0 + e;
      v = (ge < E) ? __ldg(add_feat + (size_t)ge * 2 + (s - 128)) : 0.f;
    }
    xs_rT[s][e] = v;
  }
  for (int idx = tid; idx < TE * 384; idx += 128) {
    int e = idx / 384, j = idx - e * 384;
    int r = rcvx[e] < 0 ? 0 : rcvx[e];
    float v = (j < 192) ? __ldg(node_v + (size_t)sndx[e] * 192 + j)
                        : __ldg(node_v + (size_t)r * 192 + (j - 192));
    xvT[j / 3][j % 3][e] = v;
  }
  __syncthreads();

  for (int t = tid; t < TE * 128; t += 128) {
    int v = t >> 3, e = t & 7;
    d1T[v][e] = (xvT[v][0][e] * avx[0][e] + xvT[v][1][e] * avx[1][e] +
                 xvT[v][2][e] * avx[2][e]) * RSQRT3;
  }
  __syncthreads();

  // ================= m1 (fused): K=128 (+tail 2 for Wss/Wsv) =================
  {
    float* exch = &mvT[0][0][0];    // 1536 >= 128*8
    ull acc[16];
#pragma unroll
    for (int i = 0; i < 16; i++) acc[i] = 0;
    if (wid == 0) {                  // SS: xs_r @ Wss1
      gemmR4<128, 128>(Wss1, lane, &xs_rT[0][0], TE, acc);
      accRow4(&xs_rT[128][0], ldg4(Wss1 + (size_t)128 * 128, lane), acc);
      accRow4(&xs_rT[129][0], ldg4(Wss1 + (size_t)129 * 128, lane), acc);
    } else if (wid == 1) {           // VS: d1 @ Wvs1 -> exchange
      gemmR4<128, 128>(Wvs1, lane, &d1T[0][0], TE, acc);
      float f[8];
#pragma unroll
      for (int i = 0; i < 4; i++) {
        upk8(acc + 4 * i, f);
#pragma unroll
        for (int e = 0; e < TE; e++) exch[(4 * lane + i) * TE + e] = f[e];
      }
    } else if (wid == 2) {           // q0 | q1
      gemmR4<128, 64>(Wvv1, o4v, &xvT[0][half][0], 3 * TE, acc);
    } else {                         // q2 | p
      const float* Wp = half ? Wsv1 : Wvv1;
      const float* rp = half ? &xs_rT[0][0] : &xvT[0][2][0];
      int rs = half ? TE : 3 * TE;
      gemmR4<128, 64>(Wp, o4v, rp, rs, acc);
      if (half) {                    // predicated K tail for Wsv1 (130)
        accRow4(&xs_rT[128][0], ldg4(Wsv1 + (size_t)128 * 64, o4v), acc);
        accRow4(&xs_rT[129][0], ldg4(Wsv1 + (size_t)129 * 64, o4v), acc);
        float f[8];
#pragma unroll
        for (int i = 0; i < 4; i++) {
          upk8(acc + 4 * i, f);
#pragma unroll
          for (int e = 0; e < TE; e++) pT[4 * o4v + i][e] = f[e];
        }
      }
    }
    __syncthreads();                 // exch, pT visible
    if (wid == 0) {                  // scalar epilogue
      float f[8];
#pragma unroll
      for (int i = 0; i < 4; i++) {
        int o = 4 * lane + i;
        upk8(acc + 4 * i, f);
        float bo = __ldg(b1 + o);
        if (o < 64) {
#pragma unroll
          for (int e = 0; e < TE; e++) {
            float s1 = (asx[e] * f[e] + exch[o * TE + e]) * INV1 + bo;
            ms_rT[o][e] = s1 * sigm(s1);
          }
        } else {
#pragma unroll
          for (int e = 0; e < TE; e++)
            gT[o - 64][e] = sigm((asx[e] * f[e] + exch[o * TE + e]) * INV1 + bo);
        }
      }
    }
    __syncthreads();                 // ms, gT ready; exch space about to be reused
    if (wid >= 2 && (wid == 2 || !half)) {   // vector epilogue -> mvT
      int comp = (wid == 2) ? half : 2;
      float f[8];
#pragma unroll
      for (int i = 0; i < 4; i++) {
        int o = 4 * o4v + i;
        upk8(acc + 4 * i, f);
#pragma unroll
        for (int e = 0; e < TE; e++)
          mvT[o][comp][e] =
              (pT[o][e] * avx[comp][e] + asx[e] * f[e]) * gT[o][e] * INV1;
      }
    }
  }
  __syncthreads();

  // d2
  for (int t = tid; t < TE * 64; t += 128) {
    int v = t >> 3, e = t & 7;
    d2T[v][e] = (mvT[v][0][e] * avx[0][e] + mvT[v][1][e] * avx[1][e] +
                 mvT[v][2][e] * avx[2][e]) * RSQRT3;
  }
  __syncthreads();

  // ================= m2 (fused): K=64 =================
  {
    float* exch = &d1T[0][0];        // 1024 = 128*8 (retired)
    ull acc[16];
#pragma unroll
    for (int i = 0; i < 16; i++) acc[i] = 0;
    if (wid == 0) {
      gemmR4<64, 128>(Wss2, lane, &ms_rT[0][0], TE, acc);
    } else if (wid == 1) {
      gemmR4<64, 128>(Wvs2, lane, &d2T[0][0], TE, acc);
      float f[8];
#pragma unroll
      for (int i = 0; i < 4; i++) {
        upk8(acc + 4 * i, f);
#pragma unroll
        for (int e = 0; e < TE; e++) exch[(4 * lane + i) * TE + e] = f[e];
      }
    } else if (wid == 2) {
      gemmR4<64, 64>(Wvv2, o4v, &mvT[0][half][0], 3 * TE, acc);
    } else {
      const float* Wp = half ? Wsv2 : Wvv2;
      const float* rp = half ? &ms_rT[0][0] : &mvT[0][2][0];
      int rs = half ? TE : 3 * TE;
      gemmR4<64, 64>(Wp, o4v, rp, rs, acc);
      if (half) {
        float f[8];
#pragma unroll
        for (int i = 0; i < 4; i++) {
          upk8(acc + 4 * i, f);
#pragma unroll
          for (int e = 0; e < TE; e++) pT[4 * o4v + i][e] = f[e];
        }
      }
    }
    __syncthreads();
    if (wid == 0) {                  // scalar epilogue: atomics + gates
      float f[8];
#pragma unroll
      for (int i = 0; i < 4; i++) {
        int o = 4 * lane + i;
        upk8(acc + 4 * i, f);
        float bo = __ldg(b2 + o);
        if (o < 64) {
#pragma unroll
          for (int e = 0; e < TE; e++) {
            int r = rcvx[e];
            if (r < 0) continue;
            float s2 = (asx[e] * f[e] + exch[o * TE + e]) * INV2 + bo;
            atomicAdd(g_agg_s + (size_t)r * 64 + o, s2 * sigm(s2));
          }
        } else {
#pragma unroll
          for (int e = 0; e < TE; e++)
            gT[o - 64][e] = sigm((asx[e] * f[e] + exch[o * TE + e]) * INV2 + bo);
        }
      }
    }
    __syncthreads();
    if (wid >= 2 && (wid == 2 || !half)) {  // vector epilogue: atomics
      int comp = (wid == 2) ? half : 2;
      float f[8];
#pragma unroll
      for (int i = 0; i < 4; i++) {
        int o = 4 * o4v + i;
        upk8(acc + 4 * i, f);
#pragma unroll
        for (int e = 0; e < TE; e++) {
          int r = rcvx[e];
          if (r < 0) continue;
          atomicAdd(g_agg_v + (size_t)r * 192 + o * 3 + comp,
                    (pT[o][e] * avx[comp][e] + asx[e] * f[e]) * gT[o][e] * INV2);
        }
      }
    }
  }
}

// ---------------------------------------------------------------------------
// Node kernel: same fused R=4 structure for u0, u1.
// ---------------------------------------------------------------------------
__global__ void __launch_bounds__(128, 5) node_kernel(
    const float* __restrict__ node_s, const float* __restrict__ node_v,
    const float* __restrict__ nas, const float* __restrict__ nav,
    const float* __restrict__ Wss0, const float* __restrict__ Wvs0,
    const float* __restrict__ Wsv0, const float* __restrict__ Wvv0,
    const float* __restrict__ b0,
    const float* __restrict__ Wssu, const float* __restrict__ Wvsu,
    const float* __restrict__ Wsvu, const float* __restrict__ Wvvu,
    const float* __restrict__ bu,
    float* __restrict__ out, int N)
{
  __shared__ __align__(16) float xs_rT[128][TE];
  __shared__ __align__(16) float d1T[128][TE];
  __shared__ __align__(16) float xvT[128][3][TE];
  __shared__ __align__(16) float hs_rT[64][TE];
  __shared__ __align__(16) float gT[64][TE];       // u1 exchange
  __shared__ __align__(16) float d2T[64][TE];
  __shared__ __align__(16) float hvT[64][3][TE];   // u0 exchange
  __shared__ __align__(16) float pT[64][TE];
  __shared__ float asx[TE], avx[3][TE];

  const int tid = threadIdx.x;
  const int wid = tid >> 5, lane = tid & 31;
  const int half = lane >> 4;
  const int o4v = lane & 15;
  const int n0 = blockIdx.x * TE;

  if (tid < TE) {
    int n = n0 + tid;
    bool val = n < N;
    asx[tid] = val ? nas[n] : 0.f;
#pragma unroll
    for (int i = 0; i < 3; i++) avx[i][tid] = val ? nav[n * 3 + i] : 0.f;
  }
  __syncthreads();

  for (int idx = tid; idx < TE * 128; idx += 128) {
    int e = idx >> 7, s = idx & 127;
    int n = n0 + e; if (n >= N) n = 0;
    xs_rT[s][e] = (s < 64) ? __ldg(node_s + (size_t)n * 64 + s)
                           : g_agg_s[(size_t)n * 64 + (s - 64)];
  }
  for (int idx = tid; idx < TE * 384; idx += 128) {
    int e = idx / 384, j = idx - e * 384;
    int n = n0 + e; if (n >= N) n = 0;
    float v = (j < 192) ? __ldg(node_v + (size_t)n * 192 + j)
                        : g_agg_v[(size_t)n * 192 + (j - 192)];
    xvT[j / 3][j % 3][e] = v;
  }
  __syncthreads();

  for (int t = tid; t < TE * 128; t += 128) {
    int v = t >> 3, e = t & 7;
    d1T[v][e] = (xvT[v][0][e] * avx[0][e] + xvT[v][1][e] * avx[1][e] +
                 xvT[v][2][e] * avx[2][e]) * RSQRT3;
  }
  __syncthreads();

  // ================= u0 (fused): K=128 =================
  {
    float* exch = &hvT[0][0][0];
    ull acc[16];
#pragma unroll
    for (int i = 0; i < 16; i++) acc[i] = 0;
    if (wid == 0) {
      gemmR4<128, 128>(Wss0, lane, &xs_rT[0][0], TE, acc);
    } else if (wid == 1) {
      gemmR4<128, 128>(Wvs0, lane, &d1T[0][0], TE, acc);
      float f[8];
#pragma unroll
      for (int i = 0; i < 4; i++) {
        upk8(acc + 4 * i, f);
#pragma unroll
        for (int e = 0; e < TE; e++) exch[(4 * lane + i) * TE + e] = f[e];
      }
    } else if (wid == 2) {
      gemmR4<128, 64>(Wvv0, o4v, &xvT[0][half][0], 3 * TE, acc);
    } else {
      const float* Wp = half ? Wsv0 : Wvv0;
      const float* rp = half ? &xs_rT[0][0] : &xvT[0][2][0];
      int rs = half ? TE : 3 * TE;
      gemmR4<128, 64>(Wp, o4v, rp, rs, acc);
      if (half) {
        float f[8];
#pragma unroll
        for (int i = 0; i < 4; i++) {
          upk8(acc + 4 * i, f);
#pragma unroll
          for (int e = 0; e < TE; e++) pT[4 * o4v + i][e] = f[e];
        }
      }
    }
    __syncthreads();
    if (wid == 0) {
      float f[8];
#pragma unroll
      for (int i = 0; i < 4; i++) {
        int o = 4 * lane + i;
        upk8(acc + 4 * i, f);
        float bo = __ldg(b0 + o);
        if (o < 64) {
#pragma unroll
          for (int e = 0; e < TE; e++) {
            float s1 = (asx[e] * f[e] + exch[o * TE + e]) * INV0 + bo;
            hs_rT[o][e] = s1 * sigm(s1);
          }
        } else {
#pragma unroll
          for (int e = 0; e < TE; e++)
            gT[o - 64][e] = sigm((asx[e] * f[e] + exch[o * TE + e]) * INV0 + bo);
        }
      }
    }
    __syncthreads();
    if (wid >= 2 && (wid == 2 || !half)) {
      int comp = (wid == 2) ? half : 2;
      float f[8];
#pragma unroll
      for (int i = 0; i < 4; i++) {
        int o = 4 * o4v + i;
        upk8(acc + 4 * i, f);
#pragma unroll
        for (int e = 0; e < TE; e++)
          hvT[o][comp][e] =
              (pT[o][e] * avx[comp][e] + asx[e] * f[e]) * gT[o][e] * INV0;
      }
    }
  }
  __syncthreads();

  for (int t = tid; t < TE * 64; t += 128) {
    int v = t >> 3, e = t & 7;
    d2T[v][e] = (hvT[v][0][e] * avx[0][e] + hvT[v][1][e] * avx[1][e] +
                 hvT[v][2][e] * avx[2][e]) * RSQRT3;
  }
  __syncthreads();

  // ================= u1 (fused): K=64, 64 scalar outs, no gates =================
  {
    float* exch = &gT[0][0];         // 512 = 64*8 (retired)
    ull acc[16];
#pragma unroll
    for (int i = 0; i < 16; i++) acc[i] = 0;
    if (wid == 0) {                  // SS | VS (branchless: same K, rs, LDW)
      const float* Wp = half ? Wvsu : Wssu;
      const float* rp = half ? &d2T[0][0] : &hs_rT[0][0];
      gemmR4<64, 64>(Wp, o4v, rp, TE, acc);
      if (half) {
        float f[8];
#pragma unroll
        for (int i = 0; i < 4; i++) {
          upk8(acc + 4 * i, f);
#pragma unroll
          for (int e = 0; e < TE; e++) exch[(4 * o4v + i) * TE + e] = f[e];
        }
      }
    } else if (wid == 1) {           // q0 | q1
      gemmR4<64, 64>(Wvvu, o4v, &hvT[0][half][0], 3 * TE, acc);
    } else if (wid == 2) {           // q2 | p
      const float* Wp = half ? Wsvu : Wvvu;
      const float* rp = half ? &hs_rT[0][0] : &hvT[0][2][0];
      int rs = half ? TE : 3 * TE;
      gemmR4<64, 64>(Wp, o4v, rp, rs, acc);
      if (half) {
        float f[8];
#pragma unroll
        for (int i = 0; i < 4; i++) {
          upk8(acc + 4 * i, f);
#pragma unroll
          for (int e = 0; e < TE; e++) pT[4 * o4v + i][e] = f[e];
        }
      }
    }                                // wid 3 idle (u1 is small)
    __syncthreads();
    if (wid == 0 && !half) {         // scalar residual writes
      float f[8];
#pragma unroll
      for (int i = 0; i < 4; i++) {
        int o = 4 * o4v + i;
        upk8(acc + 4 * i, f);
        float bo = __ldg(bu + o);
#pragma unroll
        for (int e = 0; e < TE; e++) {
          int n = n0 + e;
          if (n >= N) continue;
          out[(size_t)n * 256 + o] =
              __ldg(node_s + (size_t)n * 64 + o) +
              (asx[e] * f[e] + exch[o * TE + e]) * INVU + bo;
        }
      }
    } else if ((wid == 1) || (wid == 2 && !half)) {  // vector residual writes
      int comp = (wid == 1) ? half : 2;
      float f[8];
#pragma unroll
      for (int i = 0; i < 4; i++) {
        int o = 4 * o4v + i;
        upk8(acc + 4 * i, f);
#pragma unroll
        for (int e = 0; e < TE; e++) {
          int n = n0 + e;
          if (n >= N) continue;
          out[(size_t)n * 256 + 64 + o * 3 + comp] =
              __ldg(node_v + (size_t)n * 192 + o * 3 + comp) +
              (pT[o][e] * avx[comp][e] + asx[e] * f[e]) * INVU;
        }
      }
    }
  }
}

extern "C" void kernel_launch(void* const* d_in, const int* in_sizes, int n_in,
                              void* d_out, int out_size) {
  const float* node_s = (const float*)d_in[0];
  const float* node_v = (const float*)d_in[1];
  const float* nas    = (const float*)d_in[2];
  const float* nav    = (const float*)d_in[3];
  const float* eas    = (const float*)d_in[4];
  const float* eav    = (const float*)d_in[5];
  const float* add_f  = (const float*)d_in[6];
  const float* m1Wss  = (const float*)d_in[7];
  const float* m1Wvs  = (const float*)d_in[8];
  const float* m1Wsv  = (const float*)d_in[9];
  const float* m1Wvv  = (const float*)d_in[10];
  const float* m1b    = (const float*)d_in[11];
  const float* m2Wss  = (const float*)d_in[12];
  const float* m2Wvs  = (const float*)d_in[13];
  const float* m2Wsv  = (const float*)d_in[14];
  const float* m2Wvv  = (const float*)d_in[15];
  const float* m2b    = (const float*)d_in[16];
  const float* u0Wss  = (const float*)d_in[17];
  const float* u0Wvs  = (const float*)d_in[18];
  const float* u0Wsv  = (const float*)d_in[19];
  const float* u0Wvv  = (const float*)d_in[20];
  const float* u0b    = (const float*)d_in[21];
  const float* u1Wss  = (const float*)d_in[22];
  const float* u1Wvs  = (const float*)d_in[23];
  const float* u1Wsv  = (const float*)d_in[24];
  const float* u1Wvv  = (const float*)d_in[25];
  const float* u1b    = (const float*)d_in[26];
  const int* senders   = (const int*)d_in[27];
  const int* receivers = (const int*)d_in[28];

  int E = in_sizes[27];
  int N = in_sizes[0] / 64;

  void* p_s = nullptr; void* p_v = nullptr;
  cudaGetSymbolAddress(&p_s, g_agg_s);
  cudaGetSymbolAddress(&p_v, g_agg_v);
  cudaMemsetAsync(p_s, 0, (size_t)N * 64 * sizeof(float));
  cudaMemsetAsync(p_v, 0, (size_t)N * 192 * sizeof(float));

  edge_kernel<<<(E + TE - 1) / TE, 128>>>(
      node_s, node_v, eas, eav, add_f,
      m1Wss, m1Wvs, m1Wsv, m1Wvv, m1b,
      m2Wss, m2Wvs, m2Wsv, m2Wvv, m2b,
      senders, receivers, E);
  node_kernel<<<(N + TE - 1) / TE, 128>>>(
      node_s, node_v, nas, nav,
      u0Wss, u0Wvs, u0Wsv, u0Wvv, u0b,
      u1Wss, u1Wvs, u1Wsv, u1Wvv, u1b,
      (float*)d_out, N);
}